// round 2
// baseline (speedup 1.0000x reference)
#include <cuda_runtime.h>
#include <math.h>

#define N_NODES   100000
#define N_EDGES   1600000
#define NUM_GRAPHS 4096
#define HID       128
#define F_IN      11
#define F_OUT     19
#define SCAN_B    512
#define SCAN_NB   ((N_NODES + SCAN_B - 1) / SCAN_B)

// ---------------- static device scratch (no allocations allowed) ----------------
__device__ float g_hs [(size_t)N_NODES * HID];   // pre-scatter (dinv-scaled) features
__device__ float g_agg[(size_t)N_NODES * HID];   // post-aggregation features (layer1 out)
__device__ float g_dinv[N_NODES];
__device__ int   g_ecnt[N_NODES];
__device__ int   g_rowptr[N_NODES + 1];
__device__ int   g_fill[N_NODES];
__device__ int   g_csr[N_EDGES];
__device__ int   g_blksum[SCAN_NB];
__device__ float g_pool[NUM_GRAPHS * HID];
__device__ int   g_cnt[NUM_GRAPHS];

// ---------------- init: zero counters / pool, set rowptr tail ----------------
__global__ void k_init() {
    int i = blockIdx.x * blockDim.x + threadIdx.x;
    if (i < N_NODES) g_ecnt[i] = 0;
    if (i < NUM_GRAPHS) g_cnt[i] = 0;
    if (i < NUM_GRAPHS * HID) g_pool[i] = 0.0f;
    if (i == 0) g_rowptr[N_NODES] = N_EDGES;
}

// ---------------- degree histogram over dst ----------------
__global__ void k_hist(const int* __restrict__ dst) {
    int e = blockIdx.x * blockDim.x + threadIdx.x;
    if (e < N_EDGES) atomicAdd(&g_ecnt[dst[e]], 1);
}

// ---------------- 3-kernel exclusive scan of g_ecnt -> g_rowptr ----------------
__global__ void k_scan1() {
    __shared__ int warp_sums[16];
    int i = blockIdx.x * SCAN_B + threadIdx.x;
    int v = (i < N_NODES) ? g_ecnt[i] : 0;
    int lane = threadIdx.x & 31, wid = threadIdx.x >> 5;
    int incl = v;
    #pragma unroll
    for (int d = 1; d < 32; d <<= 1) {
        int t = __shfl_up_sync(0xffffffffu, incl, d);
        if (lane >= d) incl += t;
    }
    if (lane == 31) warp_sums[wid] = incl;
    __syncthreads();
    if (wid == 0) {
        int s = (lane < 16) ? warp_sums[lane] : 0;
        #pragma unroll
        for (int d = 1; d < 16; d <<= 1) {
            int t = __shfl_up_sync(0xffffffffu, s, d);
            if (lane >= d) s += t;
        }
        if (lane < 16) warp_sums[lane] = s;   // inclusive warp prefix
    }
    __syncthreads();
    int offset = (wid > 0) ? warp_sums[wid - 1] : 0;
    if (i < N_NODES) g_rowptr[i] = offset + incl - v;       // exclusive within block
    if (threadIdx.x == SCAN_B - 1) g_blksum[blockIdx.x] = offset + incl;  // block total
}

__global__ void k_scan2() {
    if (threadIdx.x == 0 && blockIdx.x == 0) {
        int acc = 0;
        for (int i = 0; i < SCAN_NB; i++) { int t = g_blksum[i]; g_blksum[i] = acc; acc += t; }
    }
}

__global__ void k_scan3() {
    int i = blockIdx.x * blockDim.x + threadIdx.x;
    if (i < N_NODES) {
        int r = g_rowptr[i] + g_blksum[i / SCAN_B];
        g_rowptr[i] = r;
        g_fill[i]   = r;
        g_dinv[i]   = rsqrtf((float)(g_ecnt[i] + 1));   // +1 self loop; always > 0
    }
}

// ---------------- CSR fill ----------------
__global__ void k_fill(const int* __restrict__ src, const int* __restrict__ dst) {
    int e = blockIdx.x * blockDim.x + threadIdx.x;
    if (e < N_EDGES) {
        int d = dst[e];
        int p = atomicAdd(&g_fill[d], 1);
        g_csr[p] = src[e];
    }
}

// ---------------- GEMM1: hs = (x @ W1) * dinv,  thread = (node, 4 features) ----------------
__global__ void k_gemm1(const float* __restrict__ x, const float* __restrict__ W1) {
    int idx = blockIdx.x * blockDim.x + threadIdx.x;
    if (idx >= N_NODES * (HID / 4)) return;
    int node = idx >> 5;          // HID/4 = 32 groups per node
    int f4   = idx & 31;
    float4 acc = make_float4(0.f, 0.f, 0.f, 0.f);
    #pragma unroll
    for (int k = 0; k < F_IN; k++) {
        float xv = __ldg(&x[node * F_IN + k]);
        float4 w = __ldg(((const float4*)(W1 + k * HID)) + f4);
        acc.x += xv * w.x; acc.y += xv * w.y; acc.z += xv * w.z; acc.w += xv * w.w;
    }
    float d = g_dinv[node];
    acc.x *= d; acc.y *= d; acc.z *= d; acc.w *= d;
    ((float4*)(g_hs + (size_t)node * HID))[f4] = acc;
}

// ---------------- aggregation: warp per node, lane owns float4 slice ----------------
// acc starts at hs[node] (self loop); gathers hs[src] coalesced (512B rows, L2-resident)
// epilogue: out = dinv[node]*acc + bias; POOL=false -> relu, write g_agg (by symbol!)
//                                        POOL=true  -> fused mean-pool accumulation
template<bool POOL>
__global__ void k_agg(const float* __restrict__ bias, const int* __restrict__ batch) {
    int warp = (blockIdx.x * blockDim.x + threadIdx.x) >> 5;
    int lane = threadIdx.x & 31;
    if (warp >= N_NODES) return;
    int node = warp;

    const float* hs = g_hs;
    float4 acc = __ldg(((const float4*)(hs + (size_t)node * HID)) + lane);  // self loop

    int beg = g_rowptr[node], end = g_rowptr[node + 1];
    for (int j = beg; j < end; j += 32) {
        int n = min(32, end - j);
        int s = (lane < n) ? g_csr[j + lane] : 0;
        int t = 0;
        for (; t + 4 <= n; t += 4) {
            int s0 = __shfl_sync(0xffffffffu, s, t + 0);
            int s1 = __shfl_sync(0xffffffffu, s, t + 1);
            int s2 = __shfl_sync(0xffffffffu, s, t + 2);
            int s3 = __shfl_sync(0xffffffffu, s, t + 3);
            float4 v0 = __ldg(((const float4*)(hs + (size_t)s0 * HID)) + lane);
            float4 v1 = __ldg(((const float4*)(hs + (size_t)s1 * HID)) + lane);
            float4 v2 = __ldg(((const float4*)(hs + (size_t)s2 * HID)) + lane);
            float4 v3 = __ldg(((const float4*)(hs + (size_t)s3 * HID)) + lane);
            acc.x += v0.x + v1.x + v2.x + v3.x;
            acc.y += v0.y + v1.y + v2.y + v3.y;
            acc.z += v0.z + v1.z + v2.z + v3.z;
            acc.w += v0.w + v1.w + v2.w + v3.w;
        }
        for (; t < n; t++) {
            int sv = __shfl_sync(0xffffffffu, s, t);
            float4 v = __ldg(((const float4*)(hs + (size_t)sv * HID)) + lane);
            acc.x += v.x; acc.y += v.y; acc.z += v.z; acc.w += v.w;
        }
    }

    float d = g_dinv[node];
    float4 b = __ldg(((const float4*)bias) + lane);
    acc.x = acc.x * d + b.x;
    acc.y = acc.y * d + b.y;
    acc.z = acc.z * d + b.z;
    acc.w = acc.w * d + b.w;
    if (!POOL) {
        // layer 1 epilogue: relu, write to g_agg (device symbol -> valid address)
        acc.x = fmaxf(acc.x, 0.f); acc.y = fmaxf(acc.y, 0.f);
        acc.z = fmaxf(acc.z, 0.f); acc.w = fmaxf(acc.w, 0.f);
        ((float4*)(g_agg + (size_t)node * HID))[lane] = acc;
    } else {
        // layer 2 epilogue: fused global mean-pool accumulation
        int g = batch[node];
        float* p = g_pool + (size_t)g * HID + lane * 4;
        atomicAdd(p + 0, acc.x);
        atomicAdd(p + 1, acc.y);
        atomicAdd(p + 2, acc.z);
        atomicAdd(p + 3, acc.w);
        if (lane == 0) atomicAdd(&g_cnt[g], 1);
    }
}

// ---------------- GEMM2: g_hs = (g_agg @ W2) * dinv ----------------
// persistent blocks, W2 (64KB) + 32 h-rows (16KB) in dynamic shared.
// thread computes 4 nodes x 4 features.
__global__ void k_gemm2(const float* __restrict__ W2) {
    extern __shared__ float sh[];
    float* shW = sh;               // [128][128]
    float* shH = sh + HID * HID;   // [32][128]
    int tid = threadIdx.x;         // 256
    int tx = tid & 31, ty = tid >> 5;   // tx: feature group, ty: node group (0..7)

    // load W2 once per block
    for (int i = tid; i < HID * HID / 4; i += 256)
        ((float4*)shW)[i] = ((const float4*)W2)[i];

    for (int tile = blockIdx.x; tile < N_NODES / 32; tile += gridDim.x) {
        int nb = tile * 32;
        __syncthreads();   // prev compute done (and W visible on first iter)
        for (int i = tid; i < 32 * HID / 4; i += 256)
            ((float4*)shH)[i] = ((const float4*)(g_agg + (size_t)nb * HID))[i];
        __syncthreads();

        float4 a0 = make_float4(0.f,0.f,0.f,0.f), a1 = a0, a2 = a0, a3 = a0;
        #pragma unroll 8
        for (int k = 0; k < HID; k++) {
            float4 w = ((float4*)(shW + k * HID))[tx];
            float h0 = shH[(ty * 4 + 0) * HID + k];
            float h1 = shH[(ty * 4 + 1) * HID + k];
            float h2 = shH[(ty * 4 + 2) * HID + k];
            float h3 = shH[(ty * 4 + 3) * HID + k];
            a0.x += h0 * w.x; a0.y += h0 * w.y; a0.z += h0 * w.z; a0.w += h0 * w.w;
            a1.x += h1 * w.x; a1.y += h1 * w.y; a1.z += h1 * w.z; a1.w += h1 * w.w;
            a2.x += h2 * w.x; a2.y += h2 * w.y; a2.z += h2 * w.z; a2.w += h2 * w.w;
            a3.x += h3 * w.x; a3.y += h3 * w.y; a3.z += h3 * w.z; a3.w += h3 * w.w;
        }
        {
            int node = nb + ty * 4 + 0; float d = g_dinv[node];
            a0.x *= d; a0.y *= d; a0.z *= d; a0.w *= d;
            ((float4*)(g_hs + (size_t)node * HID))[tx] = a0;
        }
        {
            int node = nb + ty * 4 + 1; float d = g_dinv[node];
            a1.x *= d; a1.y *= d; a1.z *= d; a1.w *= d;
            ((float4*)(g_hs + (size_t)node * HID))[tx] = a1;
        }
        {
            int node = nb + ty * 4 + 2; float d = g_dinv[node];
            a2.x *= d; a2.y *= d; a2.z *= d; a2.w *= d;
            ((float4*)(g_hs + (size_t)node * HID))[tx] = a2;
        }
        {
            int node = nb + ty * 4 + 3; float d = g_dinv[node];
            a3.x *= d; a3.y *= d; a3.z *= d; a3.w *= d;
            ((float4*)(g_hs + (size_t)node * HID))[tx] = a3;
        }
    }
}

// ---------------- final: out = (pool/cnt) @ Wlin + blin ----------------
__global__ void k_final(const float* __restrict__ Wlin, const float* __restrict__ blin,
                        float* __restrict__ out) {
    __shared__ float shp[HID];
    int g = blockIdx.x;
    int lane = threadIdx.x;   // 32
    float inv = 1.0f / fmaxf((float)g_cnt[g], 1.0f);
    float4 p = ((const float4*)(g_pool + (size_t)g * HID))[lane];
    shp[lane * 4 + 0] = p.x * inv;
    shp[lane * 4 + 1] = p.y * inv;
    shp[lane * 4 + 2] = p.z * inv;
    shp[lane * 4 + 3] = p.w * inv;
    __syncwarp();
    if (lane < F_OUT) {
        float acc = __ldg(&blin[lane]);
        #pragma unroll 16
        for (int k = 0; k < HID; k++)
            acc += shp[k] * __ldg(&Wlin[k * F_OUT + lane]);
        out[g * F_OUT + lane] = acc;
    }
}

// ---------------- launch ----------------
extern "C" void kernel_launch(void* const* d_in, const int* in_sizes, int n_in,
                              void* d_out, int out_size) {
    const float* x    = (const float*)d_in[0];
    const int*   esrc = (const int*)d_in[1];
    const int*   edst = (const int*)d_in[2];
    const int*   batch= (const int*)d_in[3];
    const float* W1   = (const float*)d_in[4];
    const float* b1   = (const float*)d_in[5];
    const float* W2   = (const float*)d_in[6];
    const float* b2   = (const float*)d_in[7];
    const float* Wlin = (const float*)d_in[8];
    const float* blin = (const float*)d_in[9];
    float* out = (float*)d_out;

    const int smem2 = (HID * HID + 32 * HID) * (int)sizeof(float);   // 80 KB
    static int smem_set = 0;
    if (!smem_set) {   // host-side attribute set; idempotent and capture-safe
        cudaFuncSetAttribute(k_gemm2, cudaFuncAttributeMaxDynamicSharedMemorySize, smem2);
        smem_set = 1;
    }

    k_init <<<(NUM_GRAPHS * HID + 255) / 256, 256>>>();
    k_hist <<<(N_EDGES + 255) / 256, 256>>>(edst);
    k_scan1<<<SCAN_NB, SCAN_B>>>();
    k_scan2<<<1, 32>>>();
    k_scan3<<<(N_NODES + 255) / 256, 256>>>();
    k_fill <<<(N_EDGES + 255) / 256, 256>>>(esrc, edst);

    // layer 1
    k_gemm1<<<(N_NODES * (HID / 4) + 255) / 256, 256>>>(x, W1);
    k_agg<false><<<(N_NODES * 32 + 255) / 256, 256>>>(b1, batch);

    // layer 2 (pool fused into aggregation epilogue)
    k_gemm2<<<296, 256, smem2>>>(W2);
    k_agg<true><<<(N_NODES * 32 + 255) / 256, 256>>>(b2, batch);

    k_final<<<NUM_GRAPHS, 32>>>(Wlin, blin, out);
}

// round 3
// speedup vs baseline: 1.7226x; 1.7226x over previous
#include <cuda_runtime.h>
#include <math.h>

#define N_NODES    100000
#define N_EDGES    1600000
#define NUM_GRAPHS 4096
#define HID        128
#define F_IN       11
#define F_OUT      19
#define P1         16      // padded input row (floats)
#define P2         24      // padded z row (floats) -> 96B, sector aligned
#define WCP        20      // padded Wc columns (col 19 = zero)
#define SCAN_B     512
#define SCAN_NB    ((N_NODES + SCAN_B - 1) / SCAN_B)

// ---------------- static device scratch ----------------
__device__ float g_xs [(size_t)N_NODES * P1];   // dinv-scaled padded input
__device__ float g_xa [(size_t)N_NODES * P1];   // aggregated input
__device__ float g_h1 [(size_t)N_NODES * HID];  // relu(layer1)
__device__ float g_z  [(size_t)N_NODES * P2];   // dinv * (h1 @ Wc)
__device__ float g_Wc [HID * WCP];              // W2 @ Wlin (padded)
__device__ float g_bc [F_OUT];                  // b2 @ Wlin + blin
__device__ float g_dinv[N_NODES];
__device__ int   g_ecnt[N_NODES];
__device__ int   g_rowptr[N_NODES + 1];
__device__ int   g_fill[N_NODES];
__device__ int   g_csr[N_EDGES];
__device__ int   g_blksum[SCAN_NB];
__device__ float g_pool[NUM_GRAPHS * F_OUT];
__device__ int   g_cnt[NUM_GRAPHS];

// ---------------- setup: zero counters/pool, Wc = W2@Wlin, bc = b2@Wlin+blin ----------------
__global__ void k_setup(const float* __restrict__ W2, const float* __restrict__ Wlin,
                        const float* __restrict__ b2, const float* __restrict__ blin) {
    int i = blockIdx.x * blockDim.x + threadIdx.x;
    if (i < N_NODES) g_ecnt[i] = 0;
    if (i < NUM_GRAPHS * F_OUT) g_pool[i] = 0.0f;
    if (i < NUM_GRAPHS) g_cnt[i] = 0;
    if (i == 0) g_rowptr[N_NODES] = N_EDGES;
    if (i < HID * WCP) {
        int k = i / WCP, f = i % WCP;
        float acc = 0.0f;
        if (f < F_OUT) {
            #pragma unroll 8
            for (int m = 0; m < HID; m++)
                acc += __ldg(&W2[k * HID + m]) * __ldg(&Wlin[m * F_OUT + f]);
        }
        g_Wc[i] = acc;   // col 19 stays 0
    }
    if (i < F_OUT) {
        float acc = __ldg(&blin[i]);
        #pragma unroll 8
        for (int m = 0; m < HID; m++)
            acc += __ldg(&b2[m]) * __ldg(&Wlin[m * F_OUT + i]);
        g_bc[i] = acc;
    }
}

// ---------------- degree histogram over dst ----------------
__global__ void k_hist(const int* __restrict__ dst) {
    int e = blockIdx.x * blockDim.x + threadIdx.x;
    if (e < N_EDGES) atomicAdd(&g_ecnt[dst[e]], 1);
}

// ---------------- scan phase 1 ----------------
__global__ void k_scan1() {
    __shared__ int warp_sums[16];
    int i = blockIdx.x * SCAN_B + threadIdx.x;
    int v = (i < N_NODES) ? g_ecnt[i] : 0;
    int lane = threadIdx.x & 31, wid = threadIdx.x >> 5;
    int incl = v;
    #pragma unroll
    for (int d = 1; d < 32; d <<= 1) {
        int t = __shfl_up_sync(0xffffffffu, incl, d);
        if (lane >= d) incl += t;
    }
    if (lane == 31) warp_sums[wid] = incl;
    __syncthreads();
    if (wid == 0) {
        int s = (lane < 16) ? warp_sums[lane] : 0;
        #pragma unroll
        for (int d = 1; d < 16; d <<= 1) {
            int t = __shfl_up_sync(0xffffffffu, s, d);
            if (lane >= d) s += t;
        }
        if (lane < 16) warp_sums[lane] = s;
    }
    __syncthreads();
    int offset = (wid > 0) ? warp_sums[wid - 1] : 0;
    if (i < N_NODES) g_rowptr[i] = offset + incl - v;
    if (threadIdx.x == SCAN_B - 1) g_blksum[blockIdx.x] = offset + incl;
}

// ---------------- scan phase 2: parallel scan of 196 block sums ----------------
__global__ void k_scan2() {
    __shared__ int ws[8];
    int t = threadIdx.x, lane = t & 31, w = t >> 5;   // 256 threads
    int v = (t < SCAN_NB) ? g_blksum[t] : 0;
    int incl = v;
    #pragma unroll
    for (int d = 1; d < 32; d <<= 1) {
        int u = __shfl_up_sync(0xffffffffu, incl, d);
        if (lane >= d) incl += u;
    }
    if (lane == 31) ws[w] = incl;
    __syncthreads();
    if (w == 0) {
        int s = (lane < 8) ? ws[lane] : 0;
        #pragma unroll
        for (int d = 1; d < 8; d <<= 1) {
            int u = __shfl_up_sync(0xffffffffu, s, d);
            if (lane >= d) s += u;
        }
        if (lane < 8) ws[lane] = s;
    }
    __syncthreads();
    int off = (w > 0) ? ws[w - 1] : 0;
    if (t < SCAN_NB) g_blksum[t] = off + incl - v;
}

// ---------------- scan phase 3 + dinv + xs = dinv*x (padded) ----------------
__global__ void k_scan3(const float* __restrict__ x) {
    int i = blockIdx.x * blockDim.x + threadIdx.x;
    if (i >= N_NODES) return;
    int r = g_rowptr[i] + g_blksum[i / SCAN_B];
    g_rowptr[i] = r;
    g_fill[i]   = r;
    float d = rsqrtf((float)(g_ecnt[i] + 1));
    g_dinv[i]   = d;
    float row[P1];
    #pragma unroll
    for (int f = 0; f < F_IN; f++) row[f] = __ldg(&x[i * F_IN + f]) * d;
    #pragma unroll
    for (int f = F_IN; f < P1; f++) row[f] = 0.0f;
    float4* dst = (float4*)(g_xs + (size_t)i * P1);
    dst[0] = make_float4(row[0], row[1], row[2], row[3]);
    dst[1] = make_float4(row[4], row[5], row[6], row[7]);
    dst[2] = make_float4(row[8], row[9], row[10], row[11]);
    dst[3] = make_float4(row[12], row[13], row[14], row[15]);
}

// ---------------- CSR fill ----------------
__global__ void k_fill(const int* __restrict__ src, const int* __restrict__ dst) {
    int e = blockIdx.x * blockDim.x + threadIdx.x;
    if (e < N_EDGES) {
        int d = dst[e];
        int p = atomicAdd(&g_fill[d], 1);
        g_csr[p] = src[e];
    }
}

// ---------------- agg1: half-warp per node over 16 padded features ----------------
__global__ void k_agg1() {
    int half = (blockIdx.x * blockDim.x + threadIdx.x) >> 4;
    int lane = threadIdx.x & 15;
    if (half >= N_NODES) return;
    int node = half;
    float acc = g_xs[(size_t)node * P1 + lane];   // self loop
    int j = g_rowptr[node], end = g_rowptr[node + 1];
    for (; j + 4 <= end; j += 4) {
        int s0 = __ldg(&g_csr[j]);
        int s1 = __ldg(&g_csr[j + 1]);
        int s2 = __ldg(&g_csr[j + 2]);
        int s3 = __ldg(&g_csr[j + 3]);
        acc += g_xs[(size_t)s0 * P1 + lane] + g_xs[(size_t)s1 * P1 + lane]
             + g_xs[(size_t)s2 * P1 + lane] + g_xs[(size_t)s3 * P1 + lane];
    }
    for (; j < end; j++)
        acc += g_xs[(size_t)__ldg(&g_csr[j]) * P1 + lane];
    g_xa[(size_t)node * P1 + lane] = acc;
}

// ---------------- GEMM1: h1 = relu(dinv*xa @ W1 + b1), warp per 2 nodes ----------------
__global__ void k_gemm1(const float* __restrict__ W1, const float* __restrict__ b1) {
    int warp = (blockIdx.x * blockDim.x + threadIdx.x) >> 5;
    int lane = threadIdx.x & 31;
    int n0 = warp * 2;
    if (n0 >= N_NODES) return;
    int n1 = min(n0 + 1, N_NODES - 1);
    float d0 = g_dinv[n0], d1 = g_dinv[n1];
    float v0 = (lane < F_IN) ? g_xa[(size_t)n0 * P1 + lane] * d0 : 0.0f;
    float v1 = (lane < F_IN) ? g_xa[(size_t)n1 * P1 + lane] * d1 : 0.0f;
    float4 bb = __ldg(((const float4*)b1) + lane);
    float4 a0 = bb, a1 = bb;
    #pragma unroll
    for (int k = 0; k < F_IN; k++) {
        float4 w = __ldg(((const float4*)(W1 + k * HID)) + lane);
        float x0 = __shfl_sync(0xffffffffu, v0, k);
        float x1 = __shfl_sync(0xffffffffu, v1, k);
        a0.x += x0 * w.x; a0.y += x0 * w.y; a0.z += x0 * w.z; a0.w += x0 * w.w;
        a1.x += x1 * w.x; a1.y += x1 * w.y; a1.z += x1 * w.z; a1.w += x1 * w.w;
    }
    a0.x = fmaxf(a0.x, 0.f); a0.y = fmaxf(a0.y, 0.f); a0.z = fmaxf(a0.z, 0.f); a0.w = fmaxf(a0.w, 0.f);
    a1.x = fmaxf(a1.x, 0.f); a1.y = fmaxf(a1.y, 0.f); a1.z = fmaxf(a1.z, 0.f); a1.w = fmaxf(a1.w, 0.f);
    ((float4*)(g_h1 + (size_t)n0 * HID))[lane] = a0;
    if (n0 + 1 < N_NODES)
        ((float4*)(g_h1 + (size_t)n1 * HID))[lane] = a1;
}

// ---------------- GEMM2': z = dinv * (h1 @ Wc)  [100k x 128 x 20] ----------------
// block 128 threads, tile 128 nodes; smem: h-tile (stride 132) + Wc
#define G2_TILE 128
#define G2_HSTRIDE 132
__global__ void k_gemm2p() {
    extern __shared__ float sh[];
    float* sH  = sh;                          // [128][132]
    float* sWc = sh + G2_TILE * G2_HSTRIDE;   // [128][20]
    int tid = threadIdx.x;                    // 128
    int base = blockIdx.x * G2_TILE;

    // load Wc
    for (int i = tid; i < HID * WCP; i += 128) sWc[i] = g_Wc[i];
    // load h tile (float4), zero-pad OOB rows
    for (int i = tid; i < G2_TILE * (HID / 4); i += 128) {
        int row = i >> 5, c = i & 31;
        int node = base + row;
        float4 v = (node < N_NODES) ? ((const float4*)(g_h1 + (size_t)node * HID))[c]
                                    : make_float4(0.f, 0.f, 0.f, 0.f);
        *(float4*)(sH + row * G2_HSTRIDE + c * 4) = v;
    }
    __syncthreads();

    int fg = tid & 3;        // 4 groups of 5 outputs
    int ng = tid >> 2;       // 0..31
    float acc[4][5];
    #pragma unroll
    for (int r = 0; r < 4; r++)
        #pragma unroll
        for (int j = 0; j < 5; j++) acc[r][j] = 0.0f;

    #pragma unroll 4
    for (int k = 0; k < HID; k++) {
        float w0 = sWc[k * WCP + fg * 5 + 0];
        float w1 = sWc[k * WCP + fg * 5 + 1];
        float w2 = sWc[k * WCP + fg * 5 + 2];
        float w3 = sWc[k * WCP + fg * 5 + 3];
        float w4 = sWc[k * WCP + fg * 5 + 4];
        #pragma unroll
        for (int r = 0; r < 4; r++) {
            float h = sH[(ng + 32 * r) * G2_HSTRIDE + k];
            acc[r][0] += h * w0; acc[r][1] += h * w1; acc[r][2] += h * w2;
            acc[r][3] += h * w3; acc[r][4] += h * w4;
        }
    }
    #pragma unroll
    for (int r = 0; r < 4; r++) {
        int node = base + ng + 32 * r;
        if (node < N_NODES) {
            float d = g_dinv[node];
            #pragma unroll
            for (int j = 0; j < 5; j++)
                g_z[(size_t)node * P2 + fg * 5 + j] = acc[r][j] * d;
        }
    }
}

// ---------------- agg2 + fused mean-pool: warp per node, lanes 0..19 ----------------
__global__ void k_agg2(const int* __restrict__ batch) {
    int warp = (blockIdx.x * blockDim.x + threadIdx.x) >> 5;
    int lane = threadIdx.x & 31;
    if (warp >= N_NODES) return;
    int node = warp;
    bool act = lane < WCP;
    float acc = act ? g_z[(size_t)node * P2 + lane] : 0.0f;  // self loop

    int beg = g_rowptr[node], end = g_rowptr[node + 1];
    for (int j = beg; j < end; j += 32) {
        int n = min(32, end - j);
        int s = (lane < n) ? __ldg(&g_csr[j + lane]) : 0;
        int t = 0;
        for (; t + 4 <= n; t += 4) {
            int s0 = __shfl_sync(0xffffffffu, s, t + 0);
            int s1 = __shfl_sync(0xffffffffu, s, t + 1);
            int s2 = __shfl_sync(0xffffffffu, s, t + 2);
            int s3 = __shfl_sync(0xffffffffu, s, t + 3);
            if (act) {
                acc += g_z[(size_t)s0 * P2 + lane] + g_z[(size_t)s1 * P2 + lane]
                     + g_z[(size_t)s2 * P2 + lane] + g_z[(size_t)s3 * P2 + lane];
            }
        }
        for (; t < n; t++) {
            int sv = __shfl_sync(0xffffffffu, s, t);
            if (act) acc += g_z[(size_t)sv * P2 + lane];
        }
    }
    float d = g_dinv[node];
    int g = batch[node];
    if (lane < F_OUT) atomicAdd(&g_pool[g * F_OUT + lane], acc * d);
    if (lane == 0) atomicAdd(&g_cnt[g], 1);
}

// ---------------- final: out = pool/cnt + bc ----------------
__global__ void k_final(float* __restrict__ out) {
    int idx = blockIdx.x * blockDim.x + threadIdx.x;
    if (idx >= NUM_GRAPHS * F_OUT) return;
    int g = idx / F_OUT, f = idx - g * F_OUT;
    float inv = 1.0f / fmaxf((float)g_cnt[g], 1.0f);
    out[idx] = g_pool[idx] * inv + g_bc[f];
}

// ---------------- launch ----------------
extern "C" void kernel_launch(void* const* d_in, const int* in_sizes, int n_in,
                              void* d_out, int out_size) {
    const float* x    = (const float*)d_in[0];
    const int*   esrc = (const int*)d_in[1];
    const int*   edst = (const int*)d_in[2];
    const int*   batch= (const int*)d_in[3];
    const float* W1   = (const float*)d_in[4];
    const float* b1   = (const float*)d_in[5];
    const float* W2   = (const float*)d_in[6];
    const float* b2   = (const float*)d_in[7];
    const float* Wlin = (const float*)d_in[8];
    const float* blin = (const float*)d_in[9];
    float* out = (float*)d_out;

    const int smem2 = (G2_TILE * G2_HSTRIDE + HID * WCP) * (int)sizeof(float);  // ~77.8 KB
    static int attr_set = 0;
    if (!attr_set) {
        cudaFuncSetAttribute(k_gemm2p, cudaFuncAttributeMaxDynamicSharedMemorySize, smem2);
        attr_set = 1;
    }

    k_setup<<<(N_NODES + 255) / 256, 256>>>(W2, Wlin, b2, blin);
    k_hist <<<(N_EDGES + 255) / 256, 256>>>(edst);
    k_scan1<<<SCAN_NB, SCAN_B>>>();
    k_scan2<<<1, 256>>>();
    k_scan3<<<(N_NODES + 255) / 256, 256>>>(x);
    k_fill <<<(N_EDGES + 255) / 256, 256>>>(esrc, edst);

    k_agg1 <<<(N_NODES * 16 + 255) / 256, 256>>>();
    k_gemm1<<<((N_NODES + 1) / 2 * 32 + 255) / 256, 256>>>(W1, b1);
    k_gemm2p<<<(N_NODES + G2_TILE - 1) / G2_TILE, 128, smem2>>>();
    k_agg2 <<<(N_NODES * 32 + 255) / 256, 256>>>(batch);
    k_final<<<(NUM_GRAPHS * F_OUT + 255) / 256, 256>>>(out);
}

// round 4
// speedup vs baseline: 2.2237x; 1.2909x over previous
#include <cuda_runtime.h>
#include <math.h>

#define N_NODES    100000
#define N_EDGES    1600000
#define NUM_GRAPHS 4096
#define HID        128
#define F_IN       11
#define F_OUT      19
#define P1         16      // padded input row (floats)
#define P2         24      // padded z row (floats)
#define WCP        20      // padded Wc columns (col 19 = zero)
#define SCAN_B     512
#define SCAN_NB    ((N_NODES + SCAN_B - 1) / SCAN_B)
#define NB_HIST    ((N_EDGES + 255) / 256)
// tail work in k_hist: pool zero | cnt zero | Wc | bc
#define TAIL_POOL  (NUM_GRAPHS * F_OUT)
#define TAIL_CNT   (TAIL_POOL + NUM_GRAPHS)
#define TAIL_WC    (TAIL_CNT + HID * WCP)
#define TAIL_BC    (TAIL_WC + F_OUT)
#define NB_TAIL    ((TAIL_BC + 255) / 256)

#define G2_TILE    128
#define G2_HSTRIDE 132

// ---------------- static device scratch (zero-initialized at load) ----------------
__device__ float g_xs [(size_t)N_NODES * P1];   // dinv-scaled padded input
__device__ float g_xa [(size_t)N_NODES * P1];   // aggregated input
__device__ float g_z  [(size_t)N_NODES * P2];   // dinv * (h1 @ Wc)
__device__ float g_Wc [HID * WCP];              // W2 @ Wlin (padded)
__device__ float g_bc [F_OUT];                  // b2 @ Wlin + blin
__device__ float g_dinv[N_NODES];
__device__ int   g_ecnt[N_NODES];               // self-cleaned by k_scan23
__device__ int   g_rowptr[N_NODES + 1];
__device__ int   g_fill[N_NODES];
__device__ int   g_csr[N_EDGES];
__device__ int   g_blksum[SCAN_NB];
__device__ float g_pool[NUM_GRAPHS * F_OUT];    // zeroed in k_hist tail
__device__ int   g_cnt[NUM_GRAPHS];             // zeroed in k_hist tail

// ---------------- hist over dst + tail: zero pool/cnt, compute Wc/bc ----------------
__global__ void k_hist(const int* __restrict__ dst,
                       const float* __restrict__ W2, const float* __restrict__ Wlin,
                       const float* __restrict__ b2, const float* __restrict__ blin) {
    int b = blockIdx.x;
    if (b < NB_HIST) {
        int e = b * 256 + threadIdx.x;
        if (e < N_EDGES) atomicAdd(&g_ecnt[__ldg(&dst[e])], 1);
        return;
    }
    int j = (b - NB_HIST) * 256 + threadIdx.x;
    if (j < TAIL_POOL) { g_pool[j] = 0.0f; return; }
    if (j < TAIL_CNT)  { g_cnt[j - TAIL_POOL] = 0; return; }
    if (j < TAIL_WC) {
        int i = j - TAIL_CNT;
        int k = i / WCP, f = i % WCP;
        float acc = 0.0f;
        if (f < F_OUT) {
            #pragma unroll 8
            for (int m = 0; m < HID; m++)
                acc += __ldg(&W2[k * HID + m]) * __ldg(&Wlin[m * F_OUT + f]);
        }
        g_Wc[i] = acc;
        return;
    }
    if (j < TAIL_BC) {
        int f = j - TAIL_WC;
        float acc = __ldg(&blin[f]);
        #pragma unroll 8
        for (int m = 0; m < HID; m++)
            acc += __ldg(&b2[m]) * __ldg(&Wlin[m * F_OUT + f]);
        g_bc[f] = acc;
    }
}

// ---------------- scan phase 1: per-block exclusive scan of g_ecnt ----------------
__global__ void k_scan1() {
    __shared__ int warp_sums[16];
    int i = blockIdx.x * SCAN_B + threadIdx.x;
    int v = (i < N_NODES) ? g_ecnt[i] : 0;
    int lane = threadIdx.x & 31, wid = threadIdx.x >> 5;
    int incl = v;
    #pragma unroll
    for (int d = 1; d < 32; d <<= 1) {
        int t = __shfl_up_sync(0xffffffffu, incl, d);
        if (lane >= d) incl += t;
    }
    if (lane == 31) warp_sums[wid] = incl;
    __syncthreads();
    if (wid == 0) {
        int s = (lane < 16) ? warp_sums[lane] : 0;
        #pragma unroll
        for (int d = 1; d < 16; d <<= 1) {
            int t = __shfl_up_sync(0xffffffffu, s, d);
            if (lane >= d) s += t;
        }
        if (lane < 16) warp_sums[lane] = s;
    }
    __syncthreads();
    int offset = (wid > 0) ? warp_sums[wid - 1] : 0;
    if (i < N_NODES) g_rowptr[i] = offset + incl - v;
    if (threadIdx.x == SCAN_B - 1) g_blksum[blockIdx.x] = offset + incl;
}

// ---------------- scan 2+3 fused: every block scans blksum in smem, then finalizes ----------------
// also: dinv, xs = dinv*x (padded), g_fill init, ecnt self-clean, rowptr tail
__global__ void k_scan23(const float* __restrict__ x) {
    __shared__ int pref[SCAN_NB];
    __shared__ int ws[8];
    int tid = threadIdx.x;                      // 256
    {
        int lane = tid & 31, w = tid >> 5;
        int v = (tid < SCAN_NB) ? g_blksum[tid] : 0;
        int incl = v;
        #pragma unroll
        for (int d = 1; d < 32; d <<= 1) {
            int u = __shfl_up_sync(0xffffffffu, incl, d);
            if (lane >= d) incl += u;
        }
        if (lane == 31) ws[w] = incl;
        __syncthreads();
        if (w == 0) {
            int s = (lane < 8) ? ws[lane] : 0;
            #pragma unroll
            for (int d = 1; d < 8; d <<= 1) {
                int u = __shfl_up_sync(0xffffffffu, s, d);
                if (lane >= d) s += u;
            }
            if (lane < 8) ws[lane] = s;
        }
        __syncthreads();
        int off = (w > 0) ? ws[w - 1] : 0;
        if (tid < SCAN_NB) pref[tid] = off + incl - v;
        __syncthreads();
    }
    int i = blockIdx.x * 256 + tid;
    if (i >= N_NODES) return;
    if (i == 0) g_rowptr[N_NODES] = N_EDGES;
    int r = g_rowptr[i] + pref[i / SCAN_B];
    g_rowptr[i] = r;
    g_fill[i]   = r;
    int e = g_ecnt[i];
    g_ecnt[i] = 0;                               // self-clean for next replay
    float d = rsqrtf((float)(e + 1));
    g_dinv[i] = d;
    float row[P1];
    #pragma unroll
    for (int f = 0; f < F_IN; f++) row[f] = __ldg(&x[i * F_IN + f]) * d;
    #pragma unroll
    for (int f = F_IN; f < P1; f++) row[f] = 0.0f;
    float4* dst = (float4*)(g_xs + (size_t)i * P1);
    dst[0] = make_float4(row[0], row[1], row[2], row[3]);
    dst[1] = make_float4(row[4], row[5], row[6], row[7]);
    dst[2] = make_float4(row[8], row[9], row[10], row[11]);
    dst[3] = make_float4(row[12], row[13], row[14], row[15]);
}

// ---------------- CSR fill ----------------
__global__ void k_fill(const int* __restrict__ src, const int* __restrict__ dst) {
    int e = blockIdx.x * blockDim.x + threadIdx.x;
    if (e < N_EDGES) {
        int d = __ldg(&dst[e]);
        int p = atomicAdd(&g_fill[d], 1);
        g_csr[p] = __ldg(&src[e]);
    }
}

// ---------------- agg1: half-warp per node over 16 padded features ----------------
__global__ void k_agg1() {
    int half = (blockIdx.x * blockDim.x + threadIdx.x) >> 4;
    int lane = threadIdx.x & 15;
    if (half >= N_NODES) return;
    int node = half;
    float acc = g_xs[(size_t)node * P1 + lane];   // self loop
    int j = g_rowptr[node], end = g_rowptr[node + 1];
    for (; j + 4 <= end; j += 4) {
        int s0 = __ldg(&g_csr[j]);
        int s1 = __ldg(&g_csr[j + 1]);
        int s2 = __ldg(&g_csr[j + 2]);
        int s3 = __ldg(&g_csr[j + 3]);
        acc += g_xs[(size_t)s0 * P1 + lane] + g_xs[(size_t)s1 * P1 + lane]
             + g_xs[(size_t)s2 * P1 + lane] + g_xs[(size_t)s3 * P1 + lane];
    }
    for (; j < end; j++)
        acc += g_xs[(size_t)__ldg(&g_csr[j]) * P1 + lane];
    g_xa[(size_t)node * P1 + lane] = acc;
}

// ---------------- fused GEMM1+GEMM2': tile of 128 nodes ----------------
// phase A: h1 = relu(dinv*xa @ W1 + b1) into smem tile (stride 132)
// phase B: z = dinv * (h1 @ Wc) to global
__global__ void k_gemm12(const float* __restrict__ W1, const float* __restrict__ b1) {
    extern __shared__ float sh[];
    float* sH  = sh;                          // [128][132]
    float* sWc = sh + G2_TILE * G2_HSTRIDE;   // [128][20]
    int tid = threadIdx.x;                    // 256
    int lane = tid & 31, w = tid >> 5;        // 8 warps
    int base = blockIdx.x * G2_TILE;

    for (int i = tid; i < HID * WCP; i += 256) sWc[i] = g_Wc[i];

    // preload W1 column-slice + bias into registers (44 + 4 regs)
    float4 w1r[F_IN];
    #pragma unroll
    for (int k = 0; k < F_IN; k++)
        w1r[k] = __ldg(((const float4*)(W1 + k * HID)) + lane);
    float4 bb = __ldg(((const float4*)b1) + lane);

    // phase A: warp w computes nodes [w*16, w*16+16)
    #pragma unroll 2
    for (int rep = 0; rep < 16; rep++) {
        int nl = w * 16 + rep;
        int node = base + nl;
        float4 a;
        if (node < N_NODES) {
            float d = g_dinv[node];
            float v = (lane < F_IN) ? g_xa[(size_t)node * P1 + lane] * d : 0.0f;
            a = bb;
            #pragma unroll
            for (int k = 0; k < F_IN; k++) {
                float xk = __shfl_sync(0xffffffffu, v, k);
                a.x += xk * w1r[k].x; a.y += xk * w1r[k].y;
                a.z += xk * w1r[k].z; a.w += xk * w1r[k].w;
            }
            a.x = fmaxf(a.x, 0.f); a.y = fmaxf(a.y, 0.f);
            a.z = fmaxf(a.z, 0.f); a.w = fmaxf(a.w, 0.f);
        } else {
            a = make_float4(0.f, 0.f, 0.f, 0.f);
        }
        *(float4*)(sH + nl * G2_HSTRIDE + lane * 4) = a;
    }
    __syncthreads();

    // phase B: thread = (node pair, 5-output group)
    int fg = tid & 3;          // 0..3 -> outputs fg*5..fg*5+4
    int nl = tid >> 2;         // 0..63 -> rows nl, nl+64
    float acc0[5] = {0,0,0,0,0}, acc1[5] = {0,0,0,0,0};
    #pragma unroll 4
    for (int k = 0; k < HID; k++) {
        float h0 = sH[nl * G2_HSTRIDE + k];
        float h1 = sH[(nl + 64) * G2_HSTRIDE + k];
        #pragma unroll
        for (int j = 0; j < 5; j++) {
            float wv = sWc[k * WCP + fg * 5 + j];
            acc0[j] += h0 * wv;
            acc1[j] += h1 * wv;
        }
    }
    int n0 = base + nl, n1 = base + nl + 64;
    if (n0 < N_NODES) {
        float d = g_dinv[n0];
        #pragma unroll
        for (int j = 0; j < 5; j++) g_z[(size_t)n0 * P2 + fg * 5 + j] = acc0[j] * d;
    }
    if (n1 < N_NODES) {
        float d = g_dinv[n1];
        #pragma unroll
        for (int j = 0; j < 5; j++) g_z[(size_t)n1 * P2 + fg * 5 + j] = acc1[j] * d;
    }
}

// ---------------- agg2 + fused mean-pool: warp per node, lanes 0..19 ----------------
__global__ void k_agg2(const int* __restrict__ batch) {
    int warp = (blockIdx.x * blockDim.x + threadIdx.x) >> 5;
    int lane = threadIdx.x & 31;
    if (warp >= N_NODES) return;
    int node = warp;
    bool act = lane < WCP;
    float acc = act ? g_z[(size_t)node * P2 + lane] : 0.0f;  // self loop

    int beg = g_rowptr[node], end = g_rowptr[node + 1];
    for (int j = beg; j < end; j += 32) {
        int n = min(32, end - j);
        int s = (lane < n) ? __ldg(&g_csr[j + lane]) : 0;
        int t = 0;
        for (; t + 4 <= n; t += 4) {
            int s0 = __shfl_sync(0xffffffffu, s, t + 0);
            int s1 = __shfl_sync(0xffffffffu, s, t + 1);
            int s2 = __shfl_sync(0xffffffffu, s, t + 2);
            int s3 = __shfl_sync(0xffffffffu, s, t + 3);
            if (act) {
                acc += g_z[(size_t)s0 * P2 + lane] + g_z[(size_t)s1 * P2 + lane]
                     + g_z[(size_t)s2 * P2 + lane] + g_z[(size_t)s3 * P2 + lane];
            }
        }
        for (; t < n; t++) {
            int sv = __shfl_sync(0xffffffffu, s, t);
            if (act) acc += g_z[(size_t)sv * P2 + lane];
        }
    }
    float d = g_dinv[node];
    int g = __ldg(&batch[node]);
    if (lane < F_OUT) atomicAdd(&g_pool[g * F_OUT + lane], acc * d);
    if (lane == 0) atomicAdd(&g_cnt[g], 1);
}

// ---------------- final: out = pool/cnt + bc ----------------
__global__ void k_final(float* __restrict__ out) {
    int idx = blockIdx.x * blockDim.x + threadIdx.x;
    if (idx >= NUM_GRAPHS * F_OUT) return;
    int g = idx / F_OUT, f = idx - g * F_OUT;
    float inv = 1.0f / fmaxf((float)g_cnt[g], 1.0f);
    out[idx] = g_pool[idx] * inv + g_bc[f];
}

// ---------------- launch ----------------
extern "C" void kernel_launch(void* const* d_in, const int* in_sizes, int n_in,
                              void* d_out, int out_size) {
    const float* x    = (const float*)d_in[0];
    const int*   esrc = (const int*)d_in[1];
    const int*   edst = (const int*)d_in[2];
    const int*   batch= (const int*)d_in[3];
    const float* W1   = (const float*)d_in[4];
    const float* b1   = (const float*)d_in[5];
    const float* W2   = (const float*)d_in[6];
    const float* b2   = (const float*)d_in[7];
    const float* Wlin = (const float*)d_in[8];
    const float* blin = (const float*)d_in[9];
    float* out = (float*)d_out;

    const int smem2 = (G2_TILE * G2_HSTRIDE + HID * WCP) * (int)sizeof(float);  // 77.8 KB
    static int attr_set = 0;
    if (!attr_set) {
        cudaFuncSetAttribute(k_gemm12, cudaFuncAttributeMaxDynamicSharedMemorySize, smem2);
        attr_set = 1;
    }

    k_hist  <<<NB_HIST + NB_TAIL, 256>>>(edst, W2, Wlin, b2, blin);
    k_scan1 <<<SCAN_NB, SCAN_B>>>();
    k_scan23<<<(N_NODES + 255) / 256, 256>>>(x);
    k_fill  <<<NB_HIST, 256>>>(esrc, edst);

    k_agg1  <<<(N_NODES * 16 + 255) / 256, 256>>>();
    k_gemm12<<<(N_NODES + G2_TILE - 1) / G2_TILE, 256, smem2>>>(W1, b1);
    k_agg2  <<<(N_NODES * 32 + 255) / 256, 256>>>(batch);
    k_final <<<(NUM_GRAPHS * F_OUT + 255) / 256, 256>>>(out);
}